// round 4
// baseline (speedup 1.0000x reference)
#include <cuda_runtime.h>

// SSIM loss, fully fused separable implementation.
// pred, gt: f32 [16,3,512,512]  -> out: f32 scalar = 1 - mean(ssim_map)
//
// Gaussian 1-D weights (sigma=1.5, K=11), normalized; literals so ptxas emits
// FFMA-imm (rt=1 on sm_103a, 2x throughput of 3-reg FFMA).

#define IMG_H 512
#define IMG_W 512
#define N_IMG 48            // B*C = 16*3
#define TH 64               // output rows per block
#define NROWS (TH + 10)     // 74 input rows per strip
#define NITER 77            // 7 * 11  (ring period 11 -> constant-folded slots)
#define SPAD 8
#define SW (IMG_W + 2 * SPAD)
#define NSTRIPS (IMG_H / TH)   // 8
#define C1F 0.0001f
#define C2F 0.0009f

#define GW0 0.00102838f
#define GW1 0.00759876f
#define GW2 0.03600078f
#define GW3 0.10936069f
#define GW4 0.21300553f
#define GW5 0.26601172f

__device__ float g_partials[N_IMG * NSTRIPS];   // 384 block partial sums

__global__ __launch_bounds__(512, 1)
void ssim_main(const float* __restrict__ pred, const float* __restrict__ gt)
{
    __shared__ float sx[2][SW];
    __shared__ float sy[2][SW];
    __shared__ float sred[16];

    const float Wt[11] = {GW0, GW1, GW2, GW3, GW4, GW5, GW4, GW3, GW2, GW1, GW0};

    const int c     = threadIdx.x;          // one thread per column
    const int strip = blockIdx.x;
    const int img   = blockIdx.y;
    const int row0  = strip * TH;
    const float* px = pred + (size_t)img * (IMG_H * IMG_W);
    const float* py = gt   + (size_t)img * (IMG_H * IMG_W);

    // zero-pad halo regions (stay zero for the whole kernel)
    if (c < SPAD) {
        sx[0][c] = 0.f; sx[1][c] = 0.f; sy[0][c] = 0.f; sy[1][c] = 0.f;
        sx[0][SPAD + IMG_W + c] = 0.f; sx[1][SPAD + IMG_W + c] = 0.f;
        sy[0][SPAD + IMG_W + c] = 0.f; sy[1][SPAD + IMG_W + c] = 0.f;
    }

    // vertical ring accumulators: 5 quantities x 11 slots, all in registers
    float a1[11], a2[11], axx[11], ayy[11], axy[11];
    #pragma unroll
    for (int j = 0; j < 11; ++j) {
        a1[j] = 0.f; a2[j] = 0.f; axx[j] = 0.f; ayy[j] = 0.f; axy[j] = 0.f;
    }

    // preload input row 0 (global row row0-5; zero outside image)
    float xc = 0.f, yc = 0.f;
    {
        const int gr = row0 - 5;
        if ((unsigned)gr < IMG_H) {
            xc = px[gr * IMG_W + c];
            yc = py[gr * IMG_W + c];
        }
    }

    float tsum = 0.f;

    #pragma unroll 1
    for (int rb = 0; rb < NITER; rb += 11) {
        #pragma unroll
        for (int i = 0; i < 11; ++i) {          // rb % 11 == 0 -> slots fold
            const int r = rb + i;
            const int b = r & 1;

            sx[b][SPAD + c] = xc;
            sy[b][SPAD + c] = yc;
            __syncthreads();

            // prefetch next row while this row computes (hides DRAM latency)
            float xn = 0.f, yn = 0.f;
            {
                const int gr = row0 - 5 + r + 1;
                if ((r + 1 < NROWS) && ((unsigned)gr < IMG_H)) {
                    xn = px[gr * IMG_W + c];
                    yn = py[gr * IMG_W + c];
                }
            }

            // horizontal 11-tap conv of 5 quantities (weights -> FFMA-imm)
            float hx = 0.f, hy = 0.f, hxx = 0.f, hyy = 0.f, hxy = 0.f;
            #pragma unroll
            for (int k = 0; k < 11; ++k) {
                const float xk = sx[b][SPAD - 5 + c + k];
                const float yk = sy[b][SPAD - 5 + c + k];
                hx  += Wt[k] * xk;
                hy  += Wt[k] * yk;
                hxx += Wt[k] * (xk * xk);
                hyy += Wt[k] * (yk * yk);
                hxy += Wt[k] * (xk * yk);
            }

            // vertical accumulate into ring (slot indices constant-folded)
            #pragma unroll
            for (int j = 0; j < 11; ++j) {
                const int s = (i + 1 + j) % 11;
                const float wv = Wt[10 - j];
                a1[s]  += wv * hx;
                a2[s]  += wv * hy;
                axx[s] += wv * hxx;
                ayy[s] += wv * hyy;
                axy[s] += wv * hxy;
            }

            // slot (i+1)%11 just received its last tap -> output row r-10
            const int s0 = (i + 1) % 11;
            const int o  = r - 10;
            if (o >= 0 && o < TH) {
                const float mu1 = a1[s0], mu2 = a2[s0];
                const float m11 = mu1 * mu1;
                const float m22 = mu2 * mu2;
                const float m12 = mu1 * mu2;
                const float v1  = axx[s0] - m11;
                const float v2  = ayy[s0] - m22;
                const float v12 = axy[s0] - m12;
                const float num = (2.f * m12 + C1F) * (2.f * v12 + C2F);
                const float den = (m11 + m22 + C1F) * (v1 + v2 + C2F);
                tsum += __fdividef(num, den);
            }
            // reset slot for its next output (also wipes invalid-row garbage)
            a1[s0] = 0.f; a2[s0] = 0.f; axx[s0] = 0.f; ayy[s0] = 0.f; axy[s0] = 0.f;

            xc = xn; yc = yn;
        }
    }

    // deterministic block reduction
    #pragma unroll
    for (int off = 16; off > 0; off >>= 1)
        tsum += __shfl_down_sync(0xffffffffu, tsum, off);
    if ((c & 31) == 0) sred[c >> 5] = tsum;
    __syncthreads();
    if (c == 0) {
        float s = 0.f;
        #pragma unroll
        for (int w = 0; w < 16; ++w) s += sred[w];
        g_partials[img * NSTRIPS + strip] = s;
    }
}

__global__ void ssim_final(float* __restrict__ out)
{
    __shared__ float red[256];
    const int t = threadIdx.x;
    float s = 0.f;
    for (int i = t; i < N_IMG * NSTRIPS; i += 256) s += g_partials[i];
    red[t] = s;
    __syncthreads();
    for (int st = 128; st > 0; st >>= 1) {
        if (t < st) red[t] += red[t + st];
        __syncthreads();
    }
    if (t == 0) out[0] = 1.0f - red[0] * (1.0f / 12582912.0f);
}

extern "C" void kernel_launch(void* const* d_in, const int* in_sizes, int n_in,
                              void* d_out, int out_size)
{
    (void)in_sizes; (void)n_in; (void)out_size;
    const float* pred = (const float*)d_in[0];
    const float* gt   = (const float*)d_in[1];

    dim3 grid(NSTRIPS, N_IMG);                 // (8, 48) = 384 blocks
    ssim_main<<<grid, IMG_W>>>(pred, gt);      // 512 threads, 1/column
    ssim_final<<<1, 256>>>((float*)d_out);
}